// round 5
// baseline (speedup 1.0000x reference)
#include <cuda_runtime.h>
#include <cuda_bf16.h>

#define N_NODES 50000
#define E_EDGES 800000
#define IN_DIM  128
#define FEAT    128   // HEADS*OUT_DIM
#define HEADS   4
#define OUT_D   32
#define NEG_SLOPE 0.2f
#define EPS_ 1e-16f

// ---------------- scratch (static device globals; no allocation) -------------
__device__ float4 g_h4[N_NODES * 32];           // h as float4 (25.6 MB)
__device__ float4 g_asrc4[N_NODES];
__device__ float4 g_adst4[N_NODES];
__device__ float4 g_s4[N_NODES];                // segment sums of exp
__device__ float4 g_ex4[E_EDGES];               // per-edge exp(alpha)
__device__ int    g_deg[N_NODES];               // degree by dst
__device__ int    g_rowstart[N_NODES];          // CSR row starts
__device__ int    g_cursor[N_NODES];            // placement cursors
__device__ int    g_eid[E_EDGES];               // CSR: original edge id
__device__ int    g_esrc[E_EDGES];              // CSR: src node

__device__ __forceinline__ void red_add_v4(float* addr, float a, float b, float c, float d) {
    asm volatile("red.global.add.v4.f32 [%0], {%1,%2,%3,%4};"
                 :: "l"(addr), "f"(a), "f"(b), "f"(c), "f"(d) : "memory");
}

// ---------------- K1: h = x @ W^T  (N x 128) --------------------------------
__global__ __launch_bounds__(256) void k_gemm(
    const float* __restrict__ x, const float* __restrict__ W)
{
    __shared__ float W_sm[FEAT][33];
    __shared__ float x_sm[64][32];

    const int tid  = threadIdx.x;
    const int lane = tid & 31;
    const int w    = tid >> 5;
    const int row0 = blockIdx.x * 64;
    float* g_hf = (float*)g_h4;

    float acc[8][4];
#pragma unroll
    for (int rr = 0; rr < 8; rr++)
#pragma unroll
        for (int j = 0; j < 4; j++) acc[rr][j] = 0.f;

    for (int kc = 0; kc < IN_DIM; kc += 32) {
#pragma unroll
        for (int it = 0; it < 16; it++) {
            int flat = it * 256 + tid;
            int o = flat >> 5, kk = flat & 31;
            W_sm[o][kk] = W[o * IN_DIM + kc + kk];
        }
#pragma unroll
        for (int it = 0; it < 8; it++) {
            int flat = it * 256 + tid;
            int r = flat >> 5, kk = flat & 31;
            int row = row0 + r;
            x_sm[r][kk] = (row < N_NODES) ? x[row * IN_DIM + kc + kk] : 0.f;
        }
        __syncthreads();

#pragma unroll
        for (int kk = 0; kk < 32; kk++) {
            float w0 = W_sm[lane      ][kk];
            float w1 = W_sm[lane + 32 ][kk];
            float w2 = W_sm[lane + 64 ][kk];
            float w3 = W_sm[lane + 96 ][kk];
#pragma unroll
            for (int rr = 0; rr < 8; rr++) {
                float xv = x_sm[w * 8 + rr][kk];
                acc[rr][0] += xv * w0;
                acc[rr][1] += xv * w1;
                acc[rr][2] += xv * w2;
                acc[rr][3] += xv * w3;
            }
        }
        __syncthreads();
    }

#pragma unroll
    for (int rr = 0; rr < 8; rr++) {
        int row = row0 + w * 8 + rr;
        if (row < N_NODES) {
#pragma unroll
            for (int j = 0; j < 4; j++)
                g_hf[row * FEAT + lane + 32 * j] = acc[rr][j];
        }
    }
}

// ---------------- K1b: per-node pre (a_src/a_dst, zero s and deg) ------------
__global__ __launch_bounds__(256) void k_node_pre(
    const float* __restrict__ att_src, const float* __restrict__ att_dst)
{
    int warp = (blockIdx.x * blockDim.x + threadIdx.x) >> 5;
    int lane = threadIdx.x & 31;
    if (warp >= N_NODES) return;
    int node = warp;
    int f0 = lane * 4;
    const float* g_hf = (const float*)g_h4;

    float h0 = g_hf[node * FEAT + f0 + 0];
    float h1 = g_hf[node * FEAT + f0 + 1];
    float h2 = g_hf[node * FEAT + f0 + 2];
    float h3 = g_hf[node * FEAT + f0 + 3];
    float ps = h0 * att_src[f0] + h1 * att_src[f0+1] + h2 * att_src[f0+2] + h3 * att_src[f0+3];
    float pd = h0 * att_dst[f0] + h1 * att_dst[f0+1] + h2 * att_dst[f0+2] + h3 * att_dst[f0+3];
#pragma unroll
    for (int off = 4; off >= 1; off >>= 1) {
        ps += __shfl_xor_sync(0xffffffffu, ps, off);
        pd += __shfl_xor_sync(0xffffffffu, pd, off);
    }
    float s1 = __shfl_sync(0xffffffffu, ps, 8),  d1 = __shfl_sync(0xffffffffu, pd, 8);
    float s2 = __shfl_sync(0xffffffffu, ps, 16), d2 = __shfl_sync(0xffffffffu, pd, 16);
    float s3 = __shfl_sync(0xffffffffu, ps, 24), d3 = __shfl_sync(0xffffffffu, pd, 24);
    if (lane == 0) {
        g_asrc4[node] = make_float4(ps, s1, s2, s3);
        g_adst4[node] = make_float4(pd, d1, d2, d3);
        g_s4[node]    = make_float4(0.f, 0.f, 0.f, 0.f);
        g_deg[node]   = 0;
    }
}

// ---------------- K2: exp(leakyrelu(alpha)) + segment sum + degree count -----
__global__ __launch_bounds__(256) void k_edge_pass(const int* __restrict__ ei)
{
    int e = blockIdx.x * blockDim.x + threadIdx.x;
    if (e >= E_EDGES) return;
    int src = ei[e];
    int dst = ei[E_EDGES + e];
    if ((unsigned)src >= N_NODES || (unsigned)dst >= N_NODES) return;
    float4 as = g_asrc4[src];
    float4 ad = g_adst4[dst];
    float v0 = as.x + ad.x; v0 = (v0 > 0.f) ? v0 : NEG_SLOPE * v0;
    float v1 = as.y + ad.y; v1 = (v1 > 0.f) ? v1 : NEG_SLOPE * v1;
    float v2 = as.z + ad.z; v2 = (v2 > 0.f) ? v2 : NEG_SLOPE * v2;
    float v3 = as.w + ad.w; v3 = (v3 > 0.f) ? v3 : NEG_SLOPE * v3;
    float e0 = __expf(v0), e1 = __expf(v1), e2 = __expf(v2), e3 = __expf(v3);
    g_ex4[e] = make_float4(e0, e1, e2, e3);
    red_add_v4(&g_s4[dst].x, e0, e1, e2, e3);
    atomicAdd(&g_deg[dst], 1);
}

// ---------------- K2b: exclusive scan of degrees (single block) --------------
__global__ __launch_bounds__(1024) void k_scan()
{
    __shared__ int sums[1024];
    const int t  = threadIdx.x;
    const int CH = (N_NODES + 1023) / 1024;   // 49
    int lo = t * CH;
    int hi = lo + CH; if (hi > N_NODES) hi = N_NODES;

    int s = 0;
    for (int i = lo; i < hi; i++) s += g_deg[i];
    sums[t] = s;
    __syncthreads();
    // Hillis-Steele inclusive scan
    for (int off = 1; off < 1024; off <<= 1) {
        int v = (t >= off) ? sums[t - off] : 0;
        __syncthreads();
        sums[t] += v;
        __syncthreads();
    }
    int run = (t > 0) ? sums[t - 1] : 0;
    for (int i = lo; i < hi; i++) {
        g_rowstart[i] = run;
        g_cursor[i]   = run;
        run += g_deg[i];
    }
}

// ---------------- K2c: CSR placement -----------------------------------------
__global__ __launch_bounds__(256) void k_place(const int* __restrict__ ei)
{
    int e = blockIdx.x * blockDim.x + threadIdx.x;
    if (e >= E_EDGES) return;
    int src = ei[e];
    int dst = ei[E_EDGES + e];
    if ((unsigned)src >= N_NODES || (unsigned)dst >= N_NODES) return;
    int pos = atomicAdd(&g_cursor[dst], 1);
    g_eid[pos]  = e;
    g_esrc[pos] = src;
}

// ---------------- K3: per-dst aggregation (warp per node) --------------------
__global__ __launch_bounds__(256) void k_agg(
    const float* __restrict__ bias, float* __restrict__ out,
    float* __restrict__ alpha_pooled)
{
    int warp = (blockIdx.x * blockDim.x + threadIdx.x) >> 5;
    int lane = threadIdx.x & 31;
    if (warp >= N_NODES) return;
    const int d = warp;
    const int start = g_rowstart[d];
    const int deg   = g_deg[d];
    const int hsel  = lane >> 3;
    const int f0    = lane * 4;

    float sv  = ((const float*)&g_s4[d])[hsel];
    float inv = 1.f / (sv + EPS_);

    float4 acc = *reinterpret_cast<const float4*>(bias + f0);

    for (int j = 0; j < deg; j++) {
        int eid = g_eid[start + j];
        int src = g_esrc[start + j];
        float ex    = ((const float*)&g_ex4[eid])[hsel];
        float alpha = ex * inv;
        float4 h = g_h4[src * 32 + lane];
        acc.x += h.x * alpha;
        acc.y += h.y * alpha;
        acc.z += h.z * alpha;
        acc.w += h.w * alpha;
        float p0 = __shfl_sync(0xffffffffu, alpha, 0);
        float p1 = __shfl_sync(0xffffffffu, alpha, 8);
        float p2 = __shfl_sync(0xffffffffu, alpha, 16);
        float p3 = __shfl_sync(0xffffffffu, alpha, 24);
        if (lane == 0) alpha_pooled[eid] = 0.25f * (p0 + p1 + p2 + p3);
    }
    *reinterpret_cast<float4*>(out + d * FEAT + f0) = acc;
}

// ---------------- launch -----------------------------------------------------
extern "C" void kernel_launch(void* const* d_in, const int* in_sizes, int n_in,
                              void* d_out, int out_size)
{
    const float* x      = (const float*)d_in[0];
    const int*   ei     = (const int*)d_in[1];
    const float* W      = (const float*)d_in[2];
    const float* attsrc = (const float*)d_in[3];
    const float* attdst = (const float*)d_in[4];
    const float* bias   = (const float*)d_in[5];

    float* out = (float*)d_out;
    float* alpha_pooled = (float*)d_out + ((size_t)out_size - E_EDGES);

    k_gemm<<<(N_NODES + 63) / 64, 256>>>(x, W);
    k_node_pre<<<(N_NODES * 32 + 255) / 256, 256>>>(attsrc, attdst);
    k_edge_pass<<<(E_EDGES + 255) / 256, 256>>>(ei);
    k_scan<<<1, 1024>>>();
    k_place<<<(E_EDGES + 255) / 256, 256>>>(ei);
    k_agg<<<(N_NODES * 32 + 255) / 256, 256>>>(bias, out, alpha_pooled);
}

// round 6
// speedup vs baseline: 1.4520x; 1.4520x over previous
#include <cuda_runtime.h>
#include <cuda_bf16.h>

#define N_NODES 50000
#define E_EDGES 800000
#define IN_DIM  128
#define FEAT    128   // HEADS*OUT_DIM
#define HEADS   4
#define OUT_D   32
#define NEG_SLOPE 0.2f
#define EPS_ 1e-16f

#define N_SBLKS ((N_NODES + 255) / 256)   // 196 scan blocks

// ---------------- scratch (static device globals; no allocation) -------------
__device__ float4 g_h4[N_NODES * 32];           // h as float4 (25.6 MB)
__device__ float4 g_asrc4[N_NODES];
__device__ float4 g_adst4[N_NODES];
__device__ float4 g_s4[N_NODES];                // segment sums of exp
__device__ float4 g_ex4[E_EDGES];               // per-edge exp(alpha)
__device__ int    g_deg[N_NODES];               // degree by dst
__device__ int    g_rowstart[N_NODES];          // CSR row starts
__device__ int    g_cursor[N_NODES];            // placement cursors
__device__ int    g_eid[E_EDGES];               // CSR: original edge id
__device__ int    g_esrc[E_EDGES];              // CSR: src node
__device__ int    g_bsum[N_SBLKS];              // scan block sums
__device__ int    g_boff[N_SBLKS];              // scan block offsets

__device__ __forceinline__ void red_add_v4(float* addr, float a, float b, float c, float d) {
    asm volatile("red.global.add.v4.f32 [%0], {%1,%2,%3,%4};"
                 :: "l"(addr), "f"(a), "f"(b), "f"(c), "f"(d) : "memory");
}

// ---------------- K1: h = x @ W^T  (N x 128) --------------------------------
__global__ __launch_bounds__(256) void k_gemm(
    const float* __restrict__ x, const float* __restrict__ W)
{
    __shared__ float W_sm[FEAT][33];
    __shared__ float x_sm[64][32];

    const int tid  = threadIdx.x;
    const int lane = tid & 31;
    const int w    = tid >> 5;
    const int row0 = blockIdx.x * 64;
    float* g_hf = (float*)g_h4;

    float acc[8][4];
#pragma unroll
    for (int rr = 0; rr < 8; rr++)
#pragma unroll
        for (int j = 0; j < 4; j++) acc[rr][j] = 0.f;

    for (int kc = 0; kc < IN_DIM; kc += 32) {
#pragma unroll
        for (int it = 0; it < 16; it++) {
            int flat = it * 256 + tid;
            int o = flat >> 5, kk = flat & 31;
            W_sm[o][kk] = W[o * IN_DIM + kc + kk];
        }
#pragma unroll
        for (int it = 0; it < 8; it++) {
            int flat = it * 256 + tid;
            int r = flat >> 5, kk = flat & 31;
            int row = row0 + r;
            x_sm[r][kk] = (row < N_NODES) ? x[row * IN_DIM + kc + kk] : 0.f;
        }
        __syncthreads();

#pragma unroll
        for (int kk = 0; kk < 32; kk++) {
            float w0 = W_sm[lane      ][kk];
            float w1 = W_sm[lane + 32 ][kk];
            float w2 = W_sm[lane + 64 ][kk];
            float w3 = W_sm[lane + 96 ][kk];
#pragma unroll
            for (int rr = 0; rr < 8; rr++) {
                float xv = x_sm[w * 8 + rr][kk];
                acc[rr][0] += xv * w0;
                acc[rr][1] += xv * w1;
                acc[rr][2] += xv * w2;
                acc[rr][3] += xv * w3;
            }
        }
        __syncthreads();
    }

#pragma unroll
    for (int rr = 0; rr < 8; rr++) {
        int row = row0 + w * 8 + rr;
        if (row < N_NODES) {
#pragma unroll
            for (int j = 0; j < 4; j++)
                g_hf[row * FEAT + lane + 32 * j] = acc[rr][j];
        }
    }
}

// ---------------- K1b: per-node pre (a_src/a_dst, zero s and deg) ------------
__global__ __launch_bounds__(256) void k_node_pre(
    const float* __restrict__ att_src, const float* __restrict__ att_dst)
{
    int warp = (blockIdx.x * blockDim.x + threadIdx.x) >> 5;
    int lane = threadIdx.x & 31;
    if (warp >= N_NODES) return;
    int node = warp;
    int f0 = lane * 4;
    const float* g_hf = (const float*)g_h4;

    float h0 = g_hf[node * FEAT + f0 + 0];
    float h1 = g_hf[node * FEAT + f0 + 1];
    float h2 = g_hf[node * FEAT + f0 + 2];
    float h3 = g_hf[node * FEAT + f0 + 3];
    float ps = h0 * att_src[f0] + h1 * att_src[f0+1] + h2 * att_src[f0+2] + h3 * att_src[f0+3];
    float pd = h0 * att_dst[f0] + h1 * att_dst[f0+1] + h2 * att_dst[f0+2] + h3 * att_dst[f0+3];
#pragma unroll
    for (int off = 4; off >= 1; off >>= 1) {
        ps += __shfl_xor_sync(0xffffffffu, ps, off);
        pd += __shfl_xor_sync(0xffffffffu, pd, off);
    }
    float s1 = __shfl_sync(0xffffffffu, ps, 8),  d1 = __shfl_sync(0xffffffffu, pd, 8);
    float s2 = __shfl_sync(0xffffffffu, ps, 16), d2 = __shfl_sync(0xffffffffu, pd, 16);
    float s3 = __shfl_sync(0xffffffffu, ps, 24), d3 = __shfl_sync(0xffffffffu, pd, 24);
    if (lane == 0) {
        g_asrc4[node] = make_float4(ps, s1, s2, s3);
        g_adst4[node] = make_float4(pd, d1, d2, d3);
        g_s4[node]    = make_float4(0.f, 0.f, 0.f, 0.f);
        g_deg[node]   = 0;
    }
}

// ---------------- K2: exp(leakyrelu(alpha)) + segment sum + degree count -----
__global__ __launch_bounds__(256) void k_edge_pass(const int* __restrict__ ei)
{
    int e = blockIdx.x * blockDim.x + threadIdx.x;
    if (e >= E_EDGES) return;
    int src = ei[e];
    int dst = ei[E_EDGES + e];
    if ((unsigned)src >= N_NODES || (unsigned)dst >= N_NODES) return;
    float4 as = g_asrc4[src];
    float4 ad = g_adst4[dst];
    float v0 = as.x + ad.x; v0 = (v0 > 0.f) ? v0 : NEG_SLOPE * v0;
    float v1 = as.y + ad.y; v1 = (v1 > 0.f) ? v1 : NEG_SLOPE * v1;
    float v2 = as.z + ad.z; v2 = (v2 > 0.f) ? v2 : NEG_SLOPE * v2;
    float v3 = as.w + ad.w; v3 = (v3 > 0.f) ? v3 : NEG_SLOPE * v3;
    float e0 = __expf(v0), e1 = __expf(v1), e2 = __expf(v2), e3 = __expf(v3);
    g_ex4[e] = make_float4(e0, e1, e2, e3);
    red_add_v4(&g_s4[dst].x, e0, e1, e2, e3);
    atomicAdd(&g_deg[dst], 1);
}

// ---------------- scan phase 1: per-block degree sums ------------------------
__global__ __launch_bounds__(256) void k_scan1()
{
    __shared__ int sm[8];
    int t = threadIdx.x;
    int i = blockIdx.x * 256 + t;
    int v = (i < N_NODES) ? g_deg[i] : 0;
#pragma unroll
    for (int off = 16; off >= 1; off >>= 1)
        v += __shfl_xor_sync(0xffffffffu, v, off);
    if ((t & 31) == 0) sm[t >> 5] = v;
    __syncthreads();
    if (t == 0) {
        int s = 0;
#pragma unroll
        for (int k = 0; k < 8; k++) s += sm[k];
        g_bsum[blockIdx.x] = s;
    }
}

// ---------------- scan phase 2: exclusive scan of block sums (1 block) -------
__global__ __launch_bounds__(256) void k_scan2()
{
    __shared__ int sm[256];
    int t = threadIdx.x;
    sm[t] = (t < N_SBLKS) ? g_bsum[t] : 0;
    __syncthreads();
    for (int off = 1; off < 256; off <<= 1) {
        int v = (t >= off) ? sm[t - off] : 0;
        __syncthreads();
        sm[t] += v;
        __syncthreads();
    }
    if (t < N_SBLKS) g_boff[t] = (t > 0) ? sm[t - 1] : 0;
}

// ---------------- scan phase 3: block-local exclusive scan + offset ----------
__global__ __launch_bounds__(256) void k_scan3()
{
    __shared__ int sm[256];
    int t = threadIdx.x;
    int i = blockIdx.x * 256 + t;
    int d = (i < N_NODES) ? g_deg[i] : 0;
    sm[t] = d;
    __syncthreads();
    for (int off = 1; off < 256; off <<= 1) {
        int v = (t >= off) ? sm[t - off] : 0;
        __syncthreads();
        sm[t] += v;
        __syncthreads();
    }
    if (i < N_NODES) {
        int rs = g_boff[blockIdx.x] + sm[t] - d;   // exclusive
        g_rowstart[i] = rs;
        g_cursor[i]   = rs;
    }
}

// ---------------- CSR placement ----------------------------------------------
__global__ __launch_bounds__(256) void k_place(const int* __restrict__ ei)
{
    int e = blockIdx.x * blockDim.x + threadIdx.x;
    if (e >= E_EDGES) return;
    int src = ei[e];
    int dst = ei[E_EDGES + e];
    if ((unsigned)src >= N_NODES || (unsigned)dst >= N_NODES) return;
    int pos = atomicAdd(&g_cursor[dst], 1);
    g_eid[pos]  = e;
    g_esrc[pos] = src;
}

// ---------------- K3: per-dst aggregation (warp per node) --------------------
__global__ __launch_bounds__(256) void k_agg(
    const float* __restrict__ bias, float* __restrict__ out,
    float* __restrict__ alpha_pooled)
{
    int warp = (blockIdx.x * blockDim.x + threadIdx.x) >> 5;
    int lane = threadIdx.x & 31;
    if (warp >= N_NODES) return;
    const int d = warp;
    const int start = g_rowstart[d];
    const int deg   = g_deg[d];
    const int hsel  = lane >> 3;
    const int f0    = lane * 4;

    float sv  = ((const float*)&g_s4[d])[hsel];
    float inv = 1.f / (sv + EPS_);

    float4 acc = *reinterpret_cast<const float4*>(bias + f0);

    for (int j = 0; j < deg; j++) {
        int eid = g_eid[start + j];
        int src = g_esrc[start + j];
        float ex    = ((const float*)&g_ex4[eid])[hsel];
        float alpha = ex * inv;
        float4 h = g_h4[src * 32 + lane];
        acc.x += h.x * alpha;
        acc.y += h.y * alpha;
        acc.z += h.z * alpha;
        acc.w += h.w * alpha;
        float p0 = __shfl_sync(0xffffffffu, alpha, 0);
        float p1 = __shfl_sync(0xffffffffu, alpha, 8);
        float p2 = __shfl_sync(0xffffffffu, alpha, 16);
        float p3 = __shfl_sync(0xffffffffu, alpha, 24);
        if (lane == 0) alpha_pooled[eid] = 0.25f * (p0 + p1 + p2 + p3);
    }
    *reinterpret_cast<float4*>(out + d * FEAT + f0) = acc;
}

// ---------------- launch -----------------------------------------------------
extern "C" void kernel_launch(void* const* d_in, const int* in_sizes, int n_in,
                              void* d_out, int out_size)
{
    const float* x      = (const float*)d_in[0];
    const int*   ei     = (const int*)d_in[1];
    const float* W      = (const float*)d_in[2];
    const float* attsrc = (const float*)d_in[3];
    const float* attdst = (const float*)d_in[4];
    const float* bias   = (const float*)d_in[5];

    float* out = (float*)d_out;
    float* alpha_pooled = (float*)d_out + ((size_t)out_size - E_EDGES);

    k_gemm<<<(N_NODES + 63) / 64, 256>>>(x, W);
    k_node_pre<<<(N_NODES * 32 + 255) / 256, 256>>>(attsrc, attdst);
    k_edge_pass<<<(E_EDGES + 255) / 256, 256>>>(ei);
    k_scan1<<<N_SBLKS, 256>>>();
    k_scan2<<<1, 256>>>();
    k_scan3<<<N_SBLKS, 256>>>();
    k_place<<<(E_EDGES + 255) / 256, 256>>>(ei);
    k_agg<<<(N_NODES * 32 + 255) / 256, 256>>>(bias, out, alpha_pooled);
}

// round 7
// speedup vs baseline: 1.6193x; 1.1152x over previous
#include <cuda_runtime.h>
#include <cuda_bf16.h>

#define N_NODES 50000
#define E_EDGES 800000
#define IN_DIM  128
#define FEAT    128   // HEADS*OUT_DIM
#define HEADS   4
#define OUT_D   32
#define NEG_SLOPE 0.2f
#define EPS_ 1e-16f

#define N_SBLKS ((N_NODES + 255) / 256)   // 196 scan blocks

// ---------------- scratch (static device globals; no allocation) -------------
__device__ float4 g_h4[N_NODES * 32];           // h as float4 (25.6 MB)
__device__ float4 g_asrc4[N_NODES];
__device__ float4 g_adst4[N_NODES];
__device__ float4 g_s4[N_NODES];                // segment sums of exp
__device__ float4 g_ex4[E_EDGES];               // per-edge exp(alpha)
__device__ float4 g_alpha4[E_EDGES];            // CSR-ordered normalized alpha
__device__ int    g_deg[N_NODES];
__device__ int    g_rowstart[N_NODES];
__device__ int    g_cursor[N_NODES];
__device__ int    g_esrc[E_EDGES];              // CSR: src node
__device__ int    g_bsum[N_SBLKS];
__device__ int    g_boff[N_SBLKS];

__device__ __forceinline__ void red_add_v4(float* addr, float a, float b, float c, float d) {
    asm volatile("red.global.add.v4.f32 [%0], {%1,%2,%3,%4};"
                 :: "l"(addr), "f"(a), "f"(b), "f"(c), "f"(d) : "memory");
}

// ---------------- K1: h = x @ W^T  (N x 128), vectorized ---------------------
// 256 threads, 64 rows/block. Thread (warp w, lane l): rows w*8+rr, cols l*4..l*4+3.
__global__ __launch_bounds__(256) void k_gemm(
    const float* __restrict__ x, const float* __restrict__ W)
{
    __shared__ float W_sm[32][132];    // [kk][o], pad 132 to break STS conflicts
    __shared__ float x_sm[64][32];     // [r][kk], rows 128B-aligned for LDS.128

    const int tid  = threadIdx.x;
    const int lane = tid & 31;
    const int w    = tid >> 5;
    const int row0 = blockIdx.x * 64;

    float4 acc[8];
#pragma unroll
    for (int rr = 0; rr < 8; rr++) acc[rr] = make_float4(0.f, 0.f, 0.f, 0.f);

    for (int kc = 0; kc < IN_DIM; kc += 32) {
        // W chunk: 128 o-rows x 32 kk. float4 GMEM load, transposed STS.
#pragma unroll
        for (int it = 0; it < 4; it++) {
            int f   = it * 256 + tid;       // 0..1023
            int o   = f >> 3;               // 0..127
            int kq  = f & 7;                // kk quad
            float4 wv = *reinterpret_cast<const float4*>(&W[o * IN_DIM + kc + kq * 4]);
            W_sm[kq * 4 + 0][o] = wv.x;
            W_sm[kq * 4 + 1][o] = wv.y;
            W_sm[kq * 4 + 2][o] = wv.z;
            W_sm[kq * 4 + 3][o] = wv.w;
        }
        // x chunk: 64 rows x 32 kk, float4 loads
#pragma unroll
        for (int it = 0; it < 2; it++) {
            int f  = it * 256 + tid;        // 0..511
            int r  = f >> 3;
            int kq = f & 7;
            int row = row0 + r;
            float4 xv = (row < N_NODES)
                ? *reinterpret_cast<const float4*>(&x[row * IN_DIM + kc + kq * 4])
                : make_float4(0.f, 0.f, 0.f, 0.f);
            *reinterpret_cast<float4*>(&x_sm[r][kq * 4]) = xv;
        }
        __syncthreads();

#pragma unroll
        for (int kq = 0; kq < 8; kq++) {
            float4 w0 = *reinterpret_cast<const float4*>(&W_sm[kq * 4 + 0][lane * 4]);
            float4 w1 = *reinterpret_cast<const float4*>(&W_sm[kq * 4 + 1][lane * 4]);
            float4 w2 = *reinterpret_cast<const float4*>(&W_sm[kq * 4 + 2][lane * 4]);
            float4 w3 = *reinterpret_cast<const float4*>(&W_sm[kq * 4 + 3][lane * 4]);
#pragma unroll
            for (int rr = 0; rr < 8; rr++) {
                float4 xv = *reinterpret_cast<const float4*>(&x_sm[w * 8 + rr][kq * 4]);
                acc[rr].x += xv.x * w0.x + xv.y * w1.x + xv.z * w2.x + xv.w * w3.x;
                acc[rr].y += xv.x * w0.y + xv.y * w1.y + xv.z * w2.y + xv.w * w3.y;
                acc[rr].z += xv.x * w0.z + xv.y * w1.z + xv.z * w2.z + xv.w * w3.z;
                acc[rr].w += xv.x * w0.w + xv.y * w1.w + xv.z * w2.w + xv.w * w3.w;
            }
        }
        __syncthreads();
    }

#pragma unroll
    for (int rr = 0; rr < 8; rr++) {
        int row = row0 + w * 8 + rr;
        if (row < N_NODES) g_h4[row * 32 + lane] = acc[rr];
    }
}

// ---------------- K1b: per-node pre (a_src/a_dst, zero s and deg) ------------
__global__ __launch_bounds__(256) void k_node_pre(
    const float* __restrict__ att_src, const float* __restrict__ att_dst)
{
    int warp = (blockIdx.x * blockDim.x + threadIdx.x) >> 5;
    int lane = threadIdx.x & 31;
    if (warp >= N_NODES) return;
    int node = warp;
    int f0 = lane * 4;

    float4 h = g_h4[node * 32 + lane];
    float4 as = *reinterpret_cast<const float4*>(&att_src[f0]);
    float4 ad = *reinterpret_cast<const float4*>(&att_dst[f0]);
    float ps = h.x * as.x + h.y * as.y + h.z * as.z + h.w * as.w;
    float pd = h.x * ad.x + h.y * ad.y + h.z * ad.z + h.w * ad.w;
#pragma unroll
    for (int off = 4; off >= 1; off >>= 1) {
        ps += __shfl_xor_sync(0xffffffffu, ps, off);
        pd += __shfl_xor_sync(0xffffffffu, pd, off);
    }
    float s1 = __shfl_sync(0xffffffffu, ps, 8),  d1 = __shfl_sync(0xffffffffu, pd, 8);
    float s2 = __shfl_sync(0xffffffffu, ps, 16), d2 = __shfl_sync(0xffffffffu, pd, 16);
    float s3 = __shfl_sync(0xffffffffu, ps, 24), d3 = __shfl_sync(0xffffffffu, pd, 24);
    if (lane == 0) {
        g_asrc4[node] = make_float4(ps, s1, s2, s3);
        g_adst4[node] = make_float4(pd, d1, d2, d3);
        g_s4[node]    = make_float4(0.f, 0.f, 0.f, 0.f);
        g_deg[node]   = 0;
    }
}

// ---------------- K2: exp(leakyrelu(alpha)) + segment sum + degree -----------
__global__ __launch_bounds__(256) void k_edge_pass(const int* __restrict__ ei)
{
    int e = blockIdx.x * blockDim.x + threadIdx.x;
    if (e >= E_EDGES) return;
    int src = ei[e];
    int dst = ei[E_EDGES + e];
    if ((unsigned)src >= N_NODES || (unsigned)dst >= N_NODES) return;
    float4 as = g_asrc4[src];
    float4 ad = g_adst4[dst];
    float v0 = as.x + ad.x; v0 = (v0 > 0.f) ? v0 : NEG_SLOPE * v0;
    float v1 = as.y + ad.y; v1 = (v1 > 0.f) ? v1 : NEG_SLOPE * v1;
    float v2 = as.z + ad.z; v2 = (v2 > 0.f) ? v2 : NEG_SLOPE * v2;
    float v3 = as.w + ad.w; v3 = (v3 > 0.f) ? v3 : NEG_SLOPE * v3;
    float e0 = __expf(v0), e1 = __expf(v1), e2 = __expf(v2), e3 = __expf(v3);
    g_ex4[e] = make_float4(e0, e1, e2, e3);
    red_add_v4(&g_s4[dst].x, e0, e1, e2, e3);
    atomicAdd(&g_deg[dst], 1);
}

// ---------------- scan phase 1: per-block degree sums ------------------------
__global__ __launch_bounds__(256) void k_scan1()
{
    __shared__ int sm[8];
    int t = threadIdx.x;
    int i = blockIdx.x * 256 + t;
    int v = (i < N_NODES) ? g_deg[i] : 0;
#pragma unroll
    for (int off = 16; off >= 1; off >>= 1)
        v += __shfl_xor_sync(0xffffffffu, v, off);
    if ((t & 31) == 0) sm[t >> 5] = v;
    __syncthreads();
    if (t == 0) {
        int s = 0;
#pragma unroll
        for (int k = 0; k < 8; k++) s += sm[k];
        g_bsum[blockIdx.x] = s;
    }
}

// ---------------- scan phase 2: exclusive scan of block sums -----------------
__global__ __launch_bounds__(256) void k_scan2()
{
    __shared__ int sm[256];
    int t = threadIdx.x;
    sm[t] = (t < N_SBLKS) ? g_bsum[t] : 0;
    __syncthreads();
    for (int off = 1; off < 256; off <<= 1) {
        int v = (t >= off) ? sm[t - off] : 0;
        __syncthreads();
        sm[t] += v;
        __syncthreads();
    }
    if (t < N_SBLKS) g_boff[t] = (t > 0) ? sm[t - 1] : 0;
}

// ---------------- scan phase 3: block-local exclusive scan + offset ----------
__global__ __launch_bounds__(256) void k_scan3()
{
    __shared__ int sm[256];
    int t = threadIdx.x;
    int i = blockIdx.x * 256 + t;
    int d = (i < N_NODES) ? g_deg[i] : 0;
    sm[t] = d;
    __syncthreads();
    for (int off = 1; off < 256; off <<= 1) {
        int v = (t >= off) ? sm[t - off] : 0;
        __syncthreads();
        sm[t] += v;
        __syncthreads();
    }
    if (i < N_NODES) {
        int rs = g_boff[blockIdx.x] + sm[t] - d;
        g_rowstart[i] = rs;
        g_cursor[i]   = rs;
    }
}

// ---------------- K2c: CSR placement + final alpha + pooled ------------------
// s is complete here, so alpha is final; pooled write is coalesced in e.
__global__ __launch_bounds__(256) void k_place(
    const int* __restrict__ ei, float* __restrict__ alpha_pooled)
{
    int e = blockIdx.x * blockDim.x + threadIdx.x;
    if (e >= E_EDGES) return;
    int src = ei[e];
    int dst = ei[E_EDGES + e];
    if ((unsigned)src >= N_NODES || (unsigned)dst >= N_NODES) return;
    float4 ex = g_ex4[e];
    float4 sv = g_s4[dst];
    float a0 = ex.x / (sv.x + EPS_);
    float a1 = ex.y / (sv.y + EPS_);
    float a2 = ex.z / (sv.z + EPS_);
    float a3 = ex.w / (sv.w + EPS_);
    alpha_pooled[e] = 0.25f * (a0 + a1 + a2 + a3);
    int pos = atomicAdd(&g_cursor[dst], 1);
    g_alpha4[pos] = make_float4(a0, a1, a2, a3);
    g_esrc[pos]   = src;
}

// ---------------- K3: per-dst aggregation (warp per node) --------------------
__global__ __launch_bounds__(256) void k_agg(
    const float* __restrict__ bias, float* __restrict__ out)
{
    int warp = (blockIdx.x * blockDim.x + threadIdx.x) >> 5;
    int lane = threadIdx.x & 31;
    if (warp >= N_NODES) return;
    const int d     = warp;
    const int start = g_rowstart[d];
    const int deg   = g_deg[d];
    const int hsel  = lane >> 3;
    const int f0    = lane * 4;

    float4 acc = *reinterpret_cast<const float4*>(bias + f0);

    for (int j = 0; j < deg; j++) {
        int   src   = g_esrc[start + j];
        float alpha = ((const float*)&g_alpha4[start + j])[hsel];
        float4 h = g_h4[src * 32 + lane];
        acc.x += h.x * alpha;
        acc.y += h.y * alpha;
        acc.z += h.z * alpha;
        acc.w += h.w * alpha;
    }
    *reinterpret_cast<float4*>(out + d * FEAT + f0) = acc;
}

// ---------------- launch -----------------------------------------------------
extern "C" void kernel_launch(void* const* d_in, const int* in_sizes, int n_in,
                              void* d_out, int out_size)
{
    const float* x      = (const float*)d_in[0];
    const int*   ei     = (const int*)d_in[1];
    const float* W      = (const float*)d_in[2];
    const float* attsrc = (const float*)d_in[3];
    const float* attdst = (const float*)d_in[4];
    const float* bias   = (const float*)d_in[5];

    float* out = (float*)d_out;
    float* alpha_pooled = (float*)d_out + ((size_t)out_size - E_EDGES);

    k_gemm<<<(N_NODES + 63) / 64, 256>>>(x, W);
    k_node_pre<<<(N_NODES * 32 + 255) / 256, 256>>>(attsrc, attdst);
    k_edge_pass<<<(E_EDGES + 255) / 256, 256>>>(ei);
    k_scan1<<<N_SBLKS, 256>>>();
    k_scan2<<<1, 256>>>();
    k_scan3<<<N_SBLKS, 256>>>();
    k_place<<<(E_EDGES + 255) / 256, 256>>>(ei, alpha_pooled);
    k_agg<<<(N_NODES * 32 + 255) / 256, 256>>>(bias, out);
}

// round 8
// speedup vs baseline: 1.7423x; 1.0760x over previous
#include <cuda_runtime.h>
#include <cuda_bf16.h>
#include <cuda_fp16.h>

#define N_NODES 50000
#define E_EDGES 800000
#define IN_DIM  128
#define FEAT    128   // HEADS*OUT_DIM
#define HEADS   4
#define OUT_D   32
#define NEG_SLOPE 0.2f
#define EPS_ 1e-16f

#define N_SBLKS ((N_NODES + 255) / 256)   // 196 scan blocks

// ---------------- scratch (static device globals; no allocation) -------------
__device__ uint2  g_hh4[N_NODES * 32];          // h as fp16 (half4 per lane), 12.8 MB
__device__ float4 g_asrc4[N_NODES];
__device__ float4 g_adst4[N_NODES];
__device__ float4 g_s4[N_NODES];                // segment sums of exp
__device__ float4 g_ex4[E_EDGES];               // per-edge exp(alpha)
__device__ float4 g_alpha4[E_EDGES];            // CSR-ordered normalized alpha
__device__ int    g_deg[N_NODES];
__device__ int    g_rowstart[N_NODES];
__device__ int    g_cursor[N_NODES];
__device__ int    g_esrc[E_EDGES];              // CSR: src node
__device__ int    g_bsum[N_SBLKS];
__device__ int    g_boff[N_SBLKS];

__device__ __forceinline__ void red_add_v4(float* addr, float a, float b, float c, float d) {
    asm volatile("red.global.add.v4.f32 [%0], {%1,%2,%3,%4};"
                 :: "l"(addr), "f"(a), "f"(b), "f"(c), "f"(d) : "memory");
}

// ---------------- K1: h = x @ W^T  + fused node epilogue ---------------------
// 256 threads, 64 rows/block. Thread (warp w, lane l): rows w*8+rr, cols l*4..l*4+3.
// Epilogue: fp16 h store, fp32 a_src/a_dst head dots, s/deg init.
__global__ __launch_bounds__(256) void k_gemm(
    const float* __restrict__ x, const float* __restrict__ W,
    const float* __restrict__ att_src, const float* __restrict__ att_dst)
{
    __shared__ float W_sm[32][132];    // [kk][o]
    __shared__ float x_sm[64][32];     // [r][kk]

    const int tid  = threadIdx.x;
    const int lane = tid & 31;
    const int w    = tid >> 5;
    const int row0 = blockIdx.x * 64;

    float4 acc[8];
#pragma unroll
    for (int rr = 0; rr < 8; rr++) acc[rr] = make_float4(0.f, 0.f, 0.f, 0.f);

    for (int kc = 0; kc < IN_DIM; kc += 32) {
#pragma unroll
        for (int it = 0; it < 4; it++) {
            int f   = it * 256 + tid;
            int o   = f >> 3;
            int kq  = f & 7;
            float4 wv = *reinterpret_cast<const float4*>(&W[o * IN_DIM + kc + kq * 4]);
            W_sm[kq * 4 + 0][o] = wv.x;
            W_sm[kq * 4 + 1][o] = wv.y;
            W_sm[kq * 4 + 2][o] = wv.z;
            W_sm[kq * 4 + 3][o] = wv.w;
        }
#pragma unroll
        for (int it = 0; it < 2; it++) {
            int f  = it * 256 + tid;
            int r  = f >> 3;
            int kq = f & 7;
            int row = row0 + r;
            float4 xv = (row < N_NODES)
                ? *reinterpret_cast<const float4*>(&x[row * IN_DIM + kc + kq * 4])
                : make_float4(0.f, 0.f, 0.f, 0.f);
            *reinterpret_cast<float4*>(&x_sm[r][kq * 4]) = xv;
        }
        __syncthreads();

#pragma unroll
        for (int kq = 0; kq < 8; kq++) {
            float4 w0 = *reinterpret_cast<const float4*>(&W_sm[kq * 4 + 0][lane * 4]);
            float4 w1 = *reinterpret_cast<const float4*>(&W_sm[kq * 4 + 1][lane * 4]);
            float4 w2 = *reinterpret_cast<const float4*>(&W_sm[kq * 4 + 2][lane * 4]);
            float4 w3 = *reinterpret_cast<const float4*>(&W_sm[kq * 4 + 3][lane * 4]);
#pragma unroll
            for (int rr = 0; rr < 8; rr++) {
                float4 xv = *reinterpret_cast<const float4*>(&x_sm[w * 8 + rr][kq * 4]);
                acc[rr].x += xv.x * w0.x + xv.y * w1.x + xv.z * w2.x + xv.w * w3.x;
                acc[rr].y += xv.x * w0.y + xv.y * w1.y + xv.z * w2.y + xv.w * w3.y;
                acc[rr].z += xv.x * w0.z + xv.y * w1.z + xv.z * w2.z + xv.w * w3.z;
                acc[rr].w += xv.x * w0.w + xv.y * w1.w + xv.z * w2.w + xv.w * w3.w;
            }
        }
        __syncthreads();
    }

    // fused epilogue
    const int f0 = lane * 4;
    const int hsel = lane >> 3;
    float4 as4 = *reinterpret_cast<const float4*>(&att_src[f0]);
    float4 ad4 = *reinterpret_cast<const float4*>(&att_dst[f0]);

#pragma unroll
    for (int rr = 0; rr < 8; rr++) {
        int row = row0 + w * 8 + rr;
        bool valid = (row < N_NODES);   // warp-uniform

        float ps = acc[rr].x * as4.x + acc[rr].y * as4.y + acc[rr].z * as4.z + acc[rr].w * as4.w;
        float pd = acc[rr].x * ad4.x + acc[rr].y * ad4.y + acc[rr].z * ad4.z + acc[rr].w * ad4.w;
#pragma unroll
        for (int off = 4; off >= 1; off >>= 1) {
            ps += __shfl_xor_sync(0xffffffffu, ps, off);
            pd += __shfl_xor_sync(0xffffffffu, pd, off);
        }
        if (valid) {
            if ((lane & 7) == 0) {
                ((float*)g_asrc4)[row * 4 + hsel] = ps;
                ((float*)g_adst4)[row * 4 + hsel] = pd;
            }
            __half2 h01 = __floats2half2_rn(acc[rr].x, acc[rr].y);
            __half2 h23 = __floats2half2_rn(acc[rr].z, acc[rr].w);
            uint2 hv;
            hv.x = *reinterpret_cast<unsigned*>(&h01);
            hv.y = *reinterpret_cast<unsigned*>(&h23);
            g_hh4[row * 32 + lane] = hv;
            if (lane == 0) {
                g_s4[row] = make_float4(0.f, 0.f, 0.f, 0.f);
                g_deg[row] = 0;
            }
        }
    }
}

// ---------------- K2: exp(leakyrelu(alpha)) + segment sum + degree -----------
__global__ __launch_bounds__(256) void k_edge_pass(const int* __restrict__ ei)
{
    int e = blockIdx.x * blockDim.x + threadIdx.x;
    if (e >= E_EDGES) return;
    int src = ei[e];
    int dst = ei[E_EDGES + e];
    if ((unsigned)src >= N_NODES || (unsigned)dst >= N_NODES) return;
    float4 as = g_asrc4[src];
    float4 ad = g_adst4[dst];
    float v0 = as.x + ad.x; v0 = (v0 > 0.f) ? v0 : NEG_SLOPE * v0;
    float v1 = as.y + ad.y; v1 = (v1 > 0.f) ? v1 : NEG_SLOPE * v1;
    float v2 = as.z + ad.z; v2 = (v2 > 0.f) ? v2 : NEG_SLOPE * v2;
    float v3 = as.w + ad.w; v3 = (v3 > 0.f) ? v3 : NEG_SLOPE * v3;
    float e0 = __expf(v0), e1 = __expf(v1), e2 = __expf(v2), e3 = __expf(v3);
    g_ex4[e] = make_float4(e0, e1, e2, e3);
    red_add_v4(&g_s4[dst].x, e0, e1, e2, e3);
    atomicAdd(&g_deg[dst], 1);
}

// ---------------- scan phase 1: per-block degree sums ------------------------
__global__ __launch_bounds__(256) void k_scan1()
{
    __shared__ int sm[8];
    int t = threadIdx.x;
    int i = blockIdx.x * 256 + t;
    int v = (i < N_NODES) ? g_deg[i] : 0;
#pragma unroll
    for (int off = 16; off >= 1; off >>= 1)
        v += __shfl_xor_sync(0xffffffffu, v, off);
    if ((t & 31) == 0) sm[t >> 5] = v;
    __syncthreads();
    if (t == 0) {
        int s = 0;
#pragma unroll
        for (int k = 0; k < 8; k++) s += sm[k];
        g_bsum[blockIdx.x] = s;
    }
}

// ---------------- scan phase 2: exclusive scan of block sums -----------------
__global__ __launch_bounds__(256) void k_scan2()
{
    __shared__ int sm[256];
    int t = threadIdx.x;
    sm[t] = (t < N_SBLKS) ? g_bsum[t] : 0;
    __syncthreads();
    for (int off = 1; off < 256; off <<= 1) {
        int v = (t >= off) ? sm[t - off] : 0;
        __syncthreads();
        sm[t] += v;
        __syncthreads();
    }
    if (t < N_SBLKS) g_boff[t] = (t > 0) ? sm[t - 1] : 0;
}

// ---------------- scan phase 3: block-local exclusive scan + offset ----------
__global__ __launch_bounds__(256) void k_scan3()
{
    __shared__ int sm[256];
    int t = threadIdx.x;
    int i = blockIdx.x * 256 + t;
    int d = (i < N_NODES) ? g_deg[i] : 0;
    sm[t] = d;
    __syncthreads();
    for (int off = 1; off < 256; off <<= 1) {
        int v = (t >= off) ? sm[t - off] : 0;
        __syncthreads();
        sm[t] += v;
        __syncthreads();
    }
    if (i < N_NODES) {
        int rs = g_boff[blockIdx.x] + sm[t] - d;
        g_rowstart[i] = rs;
        g_cursor[i]   = rs;
    }
}

// ---------------- K2c: CSR placement + final alpha + pooled ------------------
__global__ __launch_bounds__(256) void k_place(
    const int* __restrict__ ei, float* __restrict__ alpha_pooled)
{
    int e = blockIdx.x * blockDim.x + threadIdx.x;
    if (e >= E_EDGES) return;
    int src = ei[e];
    int dst = ei[E_EDGES + e];
    if ((unsigned)src >= N_NODES || (unsigned)dst >= N_NODES) return;
    float4 ex = g_ex4[e];
    float4 sv = g_s4[dst];
    float a0 = ex.x / (sv.x + EPS_);
    float a1 = ex.y / (sv.y + EPS_);
    float a2 = ex.z / (sv.z + EPS_);
    float a3 = ex.w / (sv.w + EPS_);
    alpha_pooled[e] = 0.25f * (a0 + a1 + a2 + a3);
    int pos = atomicAdd(&g_cursor[dst], 1);
    g_alpha4[pos] = make_float4(a0, a1, a2, a3);
    g_esrc[pos]   = src;
}

// ---------------- K3: per-dst aggregation (warp per node, fp16 gather) -------
__global__ __launch_bounds__(256) void k_agg(
    const float* __restrict__ bias, float* __restrict__ out)
{
    int warp = (blockIdx.x * blockDim.x + threadIdx.x) >> 5;
    int lane = threadIdx.x & 31;
    if (warp >= N_NODES) return;
    const int d     = warp;
    const int start = g_rowstart[d];
    const int deg   = g_deg[d];
    const int hsel  = lane >> 3;
    const int f0    = lane * 4;

    float4 acc = *reinterpret_cast<const float4*>(bias + f0);

    for (int j = 0; j < deg; j++) {
        int   src   = g_esrc[start + j];
        float alpha = ((const float*)&g_alpha4[start + j])[hsel];
        uint2 hv = g_hh4[src * 32 + lane];
        float2 f01 = __half22float2(*reinterpret_cast<__half2*>(&hv.x));
        float2 f23 = __half22float2(*reinterpret_cast<__half2*>(&hv.y));
        acc.x += f01.x * alpha;
        acc.y += f01.y * alpha;
        acc.z += f23.x * alpha;
        acc.w += f23.y * alpha;
    }
    *reinterpret_cast<float4*>(out + d * FEAT + f0) = acc;
}

// ---------------- launch -----------------------------------------------------
extern "C" void kernel_launch(void* const* d_in, const int* in_sizes, int n_in,
                              void* d_out, int out_size)
{
    const float* x      = (const float*)d_in[0];
    const int*   ei     = (const int*)d_in[1];
    const float* W      = (const float*)d_in[2];
    const float* attsrc = (const float*)d_in[3];
    const float* attdst = (const float*)d_in[4];
    const float* bias   = (const float*)d_in[5];

    float* out = (float*)d_out;
    float* alpha_pooled = (float*)d_out + ((size_t)out_size - E_EDGES);

    k_gemm<<<(N_NODES + 63) / 64, 256>>>(x, W, attsrc, attdst);
    k_edge_pass<<<(E_EDGES + 255) / 256, 256>>>(ei);
    k_scan1<<<N_SBLKS, 256>>>();
    k_scan2<<<1, 256>>>();
    k_scan3<<<N_SBLKS, 256>>>();
    k_place<<<(E_EDGES + 255) / 256, 256>>>(ei, alpha_pooled);
    k_agg<<<(N_NODES * 32 + 255) / 256, 256>>>(bias, out);
}